// round 4
// baseline (speedup 1.0000x reference)
#include <cuda_runtime.h>
#include <cstdint>

#define BB 64
#define SS 512
#define HH 1024
#define LL 9
#define NC 8
#define CHUNK 64

// scratch (static __device__ — no allocations)
__device__ float g_logits[BB*SS*LL];     // [B,S,L] fc outputs
__device__ float g_chunks[BB*NC*81];     // per-(batch,chunk) 9x9 log-semiring transfer matrices
__device__ float g_pb[BB];               // per-batch (norm - score)

// ---------------------------------------------------------------------------
// Kernel 1: logits[b,s,j] = dot(inputs[b,s,:], W[j,:]) + bias[j]
// 256 threads, 8 warps x 4 rows = 32 rows per block. W (36KB) staged in SMEM.
// ---------------------------------------------------------------------------
__global__ __launch_bounds__(256) void k_logits(const float* __restrict__ X,
                                                const float* __restrict__ W,
                                                const float* __restrict__ bias) {
    __shared__ float4 Wsh[LL*(HH/4)];   // 9*256 float4 = 36 KB
    const float4* W4 = reinterpret_cast<const float4*>(W);
    for (int idx = threadIdx.x; idx < LL*(HH/4); idx += 256) Wsh[idx] = W4[idx];
    __syncthreads();

    const int warp = threadIdx.x >> 5;
    const int lane = threadIdx.x & 31;
    const int row0 = blockIdx.x * 32 + warp * 4;
    const float4* X4 = reinterpret_cast<const float4*>(X);

    float acc[4][LL];
    #pragma unroll
    for (int r = 0; r < 4; r++)
        #pragma unroll
        for (int j = 0; j < LL; j++) acc[r][j] = 0.f;

    #pragma unroll
    for (int k = 0; k < 8; k++) {
        const int col = k * 32 + lane;   // float4 column, 0..255
        float4 xv[4];
        #pragma unroll
        for (int r = 0; r < 4; r++)
            xv[r] = X4[(size_t)(row0 + r) * (HH/4) + col];
        #pragma unroll
        for (int j = 0; j < LL; j++) {
            const float4 w = Wsh[j*(HH/4) + col];
            #pragma unroll
            for (int r = 0; r < 4; r++) {
                acc[r][j] += xv[r].x*w.x;
                acc[r][j] += xv[r].y*w.y;
                acc[r][j] += xv[r].z*w.z;
                acc[r][j] += xv[r].w*w.w;
            }
        }
    }

    // butterfly reduce: afterwards every lane holds the full sums
    #pragma unroll
    for (int r = 0; r < 4; r++)
        #pragma unroll
        for (int j = 0; j < LL; j++) {
            float v = acc[r][j];
            v += __shfl_xor_sync(0xffffffffu, v, 16);
            v += __shfl_xor_sync(0xffffffffu, v, 8);
            v += __shfl_xor_sync(0xffffffffu, v, 4);
            v += __shfl_xor_sync(0xffffffffu, v, 2);
            v += __shfl_xor_sync(0xffffffffu, v, 1);
            acc[r][j] = v;
        }

    // lane 0 stores 36 contiguous floats (144B run per 4 rows)
    if (lane == 0) {
        #pragma unroll
        for (int r = 0; r < 4; r++)
            #pragma unroll
            for (int j = 0; j < LL; j++)
                g_logits[(size_t)(row0 + r)*LL + j] = acc[r][j] + __ldg(&bias[j]);
    }
}

// ---------------------------------------------------------------------------
// Kernel 2: per-(batch,chunk) fold steps t0..t0+n-1 into a 9x9 transfer matrix
// in the (logsumexp,+) semiring. 96 threads; tid<81 => (i,j)=(tid/9,tid%9).
// Masked steps are exact copies (identity), matching jnp.where semantics.
// ---------------------------------------------------------------------------
__global__ __launch_bounds__(96) void k_chunks(const float* __restrict__ trans,
                                               const int* __restrict__ mask) {
    __shared__ float emit_sh[CHUNK][LL];
    __shared__ int   mask_sh[CHUNK];
    __shared__ float A[2][88];          // 81 used

    const int b  = blockIdx.x / NC;
    const int c  = blockIdx.x % NC;
    const int t0 = 1 + c * CHUNK;
    const int n  = min(SS, t0 + CHUNK) - t0;   // 64, last chunk 63
    const int tid = threadIdx.x;

    for (int idx = tid; idx < n * LL; idx += 96)
        emit_sh[idx / LL][idx % LL] =
            g_logits[((size_t)b*SS + t0 + idx/LL)*LL + (idx % LL)];
    for (int idx = tid; idx < n; idx += 96)
        mask_sh[idx] = mask[b*SS + t0 + idx];
    __syncthreads();

    const bool act = tid < 81;
    const int i = tid / LL, j = tid % LL;
    float tcol[LL];                    // trans[k][j]
    if (act) {
        #pragma unroll
        for (int k = 0; k < LL; k++) tcol[k] = trans[k*LL + j];
        // init with first step t0: M[i][j] = trans[i][j] + emit[j], or identity
        float a0;
        if (mask_sh[0] > 0) a0 = tcol[i] + emit_sh[0][j];
        else                a0 = (i == j) ? 0.f : -1e30f;
        A[0][tid] = a0;
    }
    __syncthreads();

    int p = 0;
    for (int s = 1; s < n; s++) {
        float newv = 0.f;
        if (act) {
            float v[LL];
            float mx = -1e30f;
            #pragma unroll
            for (int k = 0; k < LL; k++) {
                v[k] = A[p][i*LL + k] + tcol[k];
                mx = fmaxf(mx, v[k]);
            }
            float ssum = 0.f;
            #pragma unroll
            for (int k = 0; k < LL; k++) ssum += __expf(v[k] - mx);
            newv = emit_sh[s][j] + mx + __logf(ssum);
            if (mask_sh[s] <= 0) newv = A[p][tid];   // exact copy when masked
        }
        if (act) A[p ^ 1][tid] = newv;
        p ^= 1;
        __syncthreads();
    }

    if (act) g_chunks[(size_t)(b*NC + c)*81 + tid] = A[p][tid];
}

// ---------------------------------------------------------------------------
// Kernel 3: per-batch — gold path score (parallel reduce over t) and
// log-partition (alpha0 composed through 8 chunk matrices), writes norm-score.
// NOTE: labels are int32 (JAX x64 disabled makes .astype(int64) a no-op).
// ---------------------------------------------------------------------------
__global__ __launch_bounds__(256) void k_final(const float* __restrict__ trans,
                                               const int* __restrict__ mask,
                                               const int* __restrict__ labels,
                                               const float* __restrict__ startv,
                                               const float* __restrict__ endv) {
    const int b = blockIdx.x, tid = threadIdx.x;
    __shared__ float redf[256];
    __shared__ int   redi[256];
    __shared__ float alpha_sh[LL];

    float part = 0.f; int cnt = 0;
    for (int t = tid; t < SS; t += 256) {
        const int tag = labels[(size_t)b*SS + t];
        const int mi  = mask[b*SS + t];
        const float m = (mi > 0) ? 1.f : 0.f;
        cnt += (mi > 0);
        part += m * g_logits[((size_t)b*SS + t)*LL + tag];
        if (t >= 1) {
            const int tagp = labels[(size_t)b*SS + t - 1];
            part += m * trans[tagp*LL + tag];
        }
    }
    redf[tid] = part; redi[tid] = cnt;
    __syncthreads();
    for (int s2 = 128; s2 > 0; s2 >>= 1) {
        if (tid < s2) { redf[tid] += redf[tid + s2]; redi[tid] += redi[tid + s2]; }
        __syncthreads();
    }

    // alpha0 = feats[0] + start (mask not applied at t=0, per reference)
    if (tid < LL) alpha_sh[tid] = g_logits[((size_t)b*SS)*LL + tid] + startv[tid];
    __syncthreads();

    for (int c = 0; c < NC; c++) {
        float newv = 0.f;
        if (tid < LL) {
            const float* P = &g_chunks[(size_t)(b*NC + c)*81];
            float v[LL];
            float mx = -1e30f;
            #pragma unroll
            for (int k = 0; k < LL; k++) {
                v[k] = alpha_sh[k] + P[k*LL + tid];
                mx = fmaxf(mx, v[k]);
            }
            float s = 0.f;
            #pragma unroll
            for (int k = 0; k < LL; k++) s += __expf(v[k] - mx);
            newv = mx + __logf(s);
        }
        __syncthreads();
        if (tid < LL) alpha_sh[tid] = newv;
        __syncthreads();
    }

    if (tid == 0) {
        float mx = -1e30f;
        #pragma unroll
        for (int j = 0; j < LL; j++) mx = fmaxf(mx, alpha_sh[j] + endv[j]);
        float s = 0.f;
        #pragma unroll
        for (int j = 0; j < LL; j++) s += __expf(alpha_sh[j] + endv[j] - mx);
        const float norm = mx + __logf(s);

        int last_idx = redi[0] - 1; if (last_idx < 0) last_idx = 0;
        const int tag0 = labels[(size_t)b*SS];
        const int tagL = labels[(size_t)b*SS + last_idx];
        const float score = redf[0] + startv[tag0] + endv[tagL];
        g_pb[b] = norm - score;
    }
}

// ---------------------------------------------------------------------------
// Kernel 4: mean over 64 batches -> scalar output
// ---------------------------------------------------------------------------
__global__ void k_mean(float* __restrict__ out) {
    __shared__ float sh[BB];
    sh[threadIdx.x] = g_pb[threadIdx.x];
    __syncthreads();
    if (threadIdx.x == 0) {
        float s = 0.f;
        #pragma unroll
        for (int i = 0; i < BB; i++) s += sh[i];
        out[0] = s * (1.f / BB);
    }
}

extern "C" void kernel_launch(void* const* d_in, const int* in_sizes, int n_in,
                              void* d_out, int out_size) {
    const float* X      = (const float*)d_in[0];
    const int*   labels = (const int*)  d_in[1];   // int32 on device (JAX x64 off)
    const int*   mask   = (const int*)  d_in[2];
    const float* W      = (const float*)d_in[3];
    const float* bias   = (const float*)d_in[4];
    const float* trans  = (const float*)d_in[5];
    const float* startv = (const float*)d_in[6];
    const float* endv   = (const float*)d_in[7];

    k_logits<<<(BB*SS)/32, 256>>>(X, W, bias);
    k_chunks<<<BB*NC, 96>>>(trans, mask);
    k_final<<<BB, 256>>>(trans, mask, labels, startv, endv);
    k_mean<<<1, BB>>>((float*)d_out);
}